// round 15
// baseline (speedup 1.0000x reference)
#include <cuda_runtime.h>
#include <cuda_fp16.h>
#include <cstdint>
#include <cstddef>

#define BT   2048
#define Hh   1280
#define Ee   896
#define NEXP 64
#define TOPK 6
#define FFN  1792
#define TOT  (BT*TOPK)

typedef __half fp16;

// ---------------- device scratch ----------------
__device__ fp16 g_Wg[(size_t)NEXP*Ee*Hh];   // [exp][e][h]
__device__ fp16 g_Wu[(size_t)NEXP*Ee*Hh];
__device__ fp16 g_Wd[(size_t)NEXP*Hh*Ee];   // [exp][h][e]
__device__ fp16 g_Sg[(size_t)FFN*Hh];
__device__ fp16 g_Su[(size_t)FFN*Hh];
__device__ fp16 g_Sd[(size_t)Hh*FFN];
__device__ fp16 g_x16[(size_t)BT*Hh];
__device__ fp16 g_sh16[(size_t)BT*FFN];
__device__ fp16 g_act16[(size_t)TOT*Ee];
__device__ fp16 g_dout16[(size_t)TOT*Hh];
// router
__device__ int   g_topi[TOT];
__device__ float g_topw[TOT];
__device__ int   g_cnt[NEXP];
__device__ int   g_off[NEXP];
__device__ int   g_list[TOT];
__device__ float g_lw[TOT];
__device__ int   g_pos[TOT];

// ---------------- fused convert (x + shared weights) + zero counters ----------------
__global__ void cvt_all(const float* __restrict__ x,
                        const float* __restrict__ wsg,
                        const float* __restrict__ wsu,
                        const float* __restrict__ wsd) {
    if (blockIdx.x == 0 && threadIdx.x < NEXP) g_cnt[threadIdx.x] = 0;
    const int C0 = BT*Hh/4;            // x
    const int C1 = C0 + FFN*Hh/4;      // sg
    const int C2 = C1 + FFN*Hh/4;      // su
    const int C3 = C2 + Hh*FFN/4;      // sd
    int i = blockIdx.x * blockDim.x + threadIdx.x;
    if (i >= C3) return;
    const float* src; fp16* dst; int j;
    if (i < C0)      { src = x;   dst = g_x16; j = i; }
    else if (i < C1) { src = wsg; dst = g_Sg;  j = i - C0; }
    else if (i < C2) { src = wsu; dst = g_Su;  j = i - C1; }
    else             { src = wsd; dst = g_Sd;  j = i - C2; }
    float4 v = ((const float4*)src)[j];
    __half2 a = __halves2half2(__float2half_rn(v.x), __float2half_rn(v.y));
    __half2 b = __halves2half2(__float2half_rn(v.z), __float2half_rn(v.w));
    uint2 p; p.x = *(uint32_t*)&a; p.y = *(uint32_t*)&b;
    ((uint2*)dst)[j] = p;
}

// ---------------- fused router GEMM + top-k ----------------
__global__ __launch_bounds__(256) void router_fused(
    const float* __restrict__ A, const float* __restrict__ B)
{
    const int m0 = blockIdx.x * 64;
    __shared__ __align__(16) float As[16][68];
    __shared__ __align__(16) float Bs[16][68];
    __shared__ float L[64][65];
    const int tid = threadIdx.x;
    const int tx = tid & 15, ty = tid >> 4;
    float acc[4][4];
    #pragma unroll
    for (int i = 0; i < 4; i++) for (int j = 0; j < 4; j++) acc[i][j] = 0.f;
    const int aCol = tid & 15, aRow0 = tid >> 4;
    for (int k0 = 0; k0 < Hh; k0 += 16) {
        #pragma unroll
        for (int i = 0; i < 4; i++)
            As[aCol][aRow0 + 16*i] = A[(size_t)(m0 + aRow0 + 16*i)*Hh + k0 + aCol];
        #pragma unroll
        for (int i = 0; i < 4; i++)
            Bs[aCol][aRow0 + 16*i] = B[(size_t)(aRow0 + 16*i)*Hh + k0 + aCol];
        __syncthreads();
        #pragma unroll
        for (int kk = 0; kk < 16; kk++) {
            float4 a4 = *(const float4*)&As[kk][ty*4];
            float4 b4 = *(const float4*)&Bs[kk][tx*4];
            float av[4] = {a4.x,a4.y,a4.z,a4.w};
            float bv[4] = {b4.x,b4.y,b4.z,b4.w};
            #pragma unroll
            for (int i = 0; i < 4; i++) for (int j = 0; j < 4; j++) acc[i][j] += av[i]*bv[j];
        }
        __syncthreads();
    }
    #pragma unroll
    for (int i = 0; i < 4; i++)
        #pragma unroll
        for (int j = 0; j < 4; j++)
            L[ty*4 + i][tx*4 + j] = acc[i][j];
    __syncthreads();

    const int lane = tid & 31, wid = tid >> 5;
    const float NEG = __int_as_float(0xff800000);
    for (int s = 0; s < 8; s++) {
        int tl = wid * 8 + s;
        int t  = m0 + tl;
        float v0 = L[tl][lane];
        float v1 = L[tl][32 + lane];
        int i0 = lane, i1 = lane + 32;
        float bv[TOPK]; int bi[TOPK];
        #pragma unroll
        for (int k = 0; k < TOPK; k++) {
            float mv; int mi;
            if (v0 > v1 || (v0 == v1 && i0 < i1)) { mv = v0; mi = i0; } else { mv = v1; mi = i1; }
            #pragma unroll
            for (int o = 16; o > 0; o >>= 1) {
                float ov = __shfl_xor_sync(0xffffffffu, mv, o);
                int   oi = __shfl_xor_sync(0xffffffffu, mi, o);
                if (ov > mv || (ov == mv && oi < mi)) { mv = ov; mi = oi; }
            }
            bv[k] = mv; bi[k] = mi;
            if (i0 == mi) v0 = NEG;
            if (i1 == mi) v1 = NEG;
        }
        float mx = bv[0];
        float sum = 0.f, ev[TOPK];
        #pragma unroll
        for (int k = 0; k < TOPK; k++) { ev[k] = __expf(bv[k] - mx); sum += ev[k]; }
        if (lane < TOPK) {
            g_topi[t*TOPK + lane] = bi[lane];
            g_topw[t*TOPK + lane] = ev[lane] / sum;
            atomicAdd(&g_cnt[bi[lane]], 1);
        }
    }
}

// ---------------- build lists (scan folded in) ----------------
__global__ void build_lists() {
    int e = blockIdx.x;
    int tid = threadIdx.x;
    int lane = tid & 31, wid = tid >> 5;
    __shared__ int wcnt[8], wpre[8], stot, base_s;
    if (tid == 0) {
        int a = 0;
        for (int n = 0; n < e; n++) a += g_cnt[n];
        base_s = a;
        g_off[e] = a;
    }
    __syncthreads();
    int base = base_s;
    int run = 0;
    for (int s0 = 0; s0 < TOT; s0 += 256) {
        int s = s0 + tid;
        bool p = (s < TOT) && (g_topi[s] == e);
        unsigned b = __ballot_sync(0xffffffffu, p);
        int wp = __popc(b & ((1u << lane) - 1u));
        if (lane == 0) wcnt[wid] = __popc(b);
        __syncthreads();
        if (tid == 0) {
            int a = 0;
            for (int w = 0; w < 8; w++) { wpre[w] = a; a += wcnt[w]; }
            stot = a;
        }
        __syncthreads();
        if (p) {
            int pos = base + run + wpre[wid] + wp;
            g_list[pos] = s / TOPK;
            g_lw[pos]   = g_topw[s];
            g_pos[s]    = pos;
        }
        run += stot;
        __syncthreads();
    }
}

// ---------------- vectorized 64x64 transpose-convert repack ----------------
template<int NARR>
__global__ __launch_bounds__(256) void repack64(
    const float* __restrict__ s0, const float* __restrict__ s1,
    fp16* __restrict__ d0, fp16* __restrict__ d1,
    int S1, size_t S2, int S3)
{
    __shared__ float smA[64][65];
    __shared__ float smB[NARR == 2 ? 64 : 1][NARR == 2 ? 65 : 1];
    const int F = blockIdx.x;
    const int dd0 = blockIdx.y * 64;
    const int t = threadIdx.x;

    #pragma unroll
    for (int i = 0; i < 4; i++) {
        int idx = i*256 + t;
        int r = idx >> 4, q = idx & 15;
        size_t so = (size_t)(dd0 + r) * S1 + (size_t)F * 64 + q*4;
        float4 v = *(const float4*)(s0 + so);
        smA[q*4+0][r] = v.x; smA[q*4+1][r] = v.y;
        smA[q*4+2][r] = v.z; smA[q*4+3][r] = v.w;
        if (NARR == 2) {
            float4 u = *(const float4*)(s1 + so);
            smB[q*4+0][r] = u.x; smB[q*4+1][r] = u.y;
            smB[q*4+2][r] = u.z; smB[q*4+3][r] = u.w;
        }
    }
    __syncthreads();

    #pragma unroll
    for (int i = 0; i < 2; i++) {
        int idx = i*256 + t;
        int xr = idx >> 3, hb = idx & 7;
        fp16 h8[8];
        #pragma unroll
        for (int c = 0; c < 8; c++) h8[c] = __float2half_rn(smA[xr][hb*8 + c]);
        size_t doff = (size_t)xr * S2 + (size_t)F * S3 + dd0 + hb*8;
        *(uint4*)(d0 + doff) = *(uint4*)h8;
        if (NARR == 2) {
            #pragma unroll
            for (int c = 0; c < 8; c++) h8[c] = __float2half_rn(smB[xr][hb*8 + c]);
            *(uint4*)(d1 + doff) = *(uint4*)h8;
        }
    }
}

// ---------------- MMA / cp.async helpers ----------------
__device__ __forceinline__ void ldsm_x4(uint32_t* r, const void* p) {
    uint32_t a = (uint32_t)__cvta_generic_to_shared(p);
    asm volatile("ldmatrix.sync.aligned.m8n8.x4.shared.b16 {%0,%1,%2,%3}, [%4];"
        : "=r"(r[0]), "=r"(r[1]), "=r"(r[2]), "=r"(r[3]) : "r"(a));
}
__device__ __forceinline__ void mma16816h(float* d, const uint32_t* a, const uint32_t* b) {
    asm volatile("mma.sync.aligned.m16n8k16.row.col.f32.f16.f16.f32 "
        "{%0,%1,%2,%3}, {%4,%5,%6,%7}, {%8,%9}, {%0,%1,%2,%3};"
        : "+f"(d[0]), "+f"(d[1]), "+f"(d[2]), "+f"(d[3])
        : "r"(a[0]), "r"(a[1]), "r"(a[2]), "r"(a[3]), "r"(b[0]), "r"(b[1]));
}
__device__ __forceinline__ void cp16(uint32_t dst, const void* src, bool pred) {
    int sz = pred ? 16 : 0;
    asm volatile("cp.async.ca.shared.global [%0], [%1], 16, %2;"
        :: "r"(dst), "l"(src), "r"(sz));
}
__device__ __forceinline__ void cp_commit() { asm volatile("cp.async.commit_group;" ::: "memory"); }
template<int N> __device__ __forceinline__ void cp_wait() { asm volatile("cp.async.wait_group %0;" :: "n"(N) : "memory"); }

// ---------------- single-fp16 MMA GEMM ----------------
// MT x 64 x 32 tile, 8 warps, 3-stage cp.async ring, single sync per k-iter, 2 CTAs/SM.
// MT=128: warps 4x2 (warp 32x32). MT=64: warps 2x4 (warp 32x16).
// MODE: 0 fp32 store, 1 dual-B silu(g)*u -> fp16 store, 2 weighted slot fp16 store
// AMODE: 0 plain rows, 1 gather via g_list (store rows = slots), 2 rows are slots
template<int MODE, int AMODE, int MT>
__global__ __launch_bounds__(256, 2) void mma2(
    const fp16* __restrict__ A, int lda,
    const fp16* __restrict__ B0, const fp16* __restrict__ B1,
    size_t bStride,
    float* __restrict__ C, fp16* __restrict__ Cq,
    int ldc, int M, int K, int ntiles)
{
    constexpr int NB  = (MODE == 1) ? 2 : 1;
    constexpr int FN  = (MT == 128) ? 4 : 2;    // fn blocks (8 cols each) per warp
    constexpr int ACH = MT / 64;                // A cp.async chunks per thread
    constexpr int OFF_B = MT*40;
    constexpr int STG   = MT*40 + NB*64*40;
    extern __shared__ __align__(16) fp16 sm[];

    const int mt = blockIdx.x;
    int e, nt;
    if (AMODE != 0) { e = blockIdx.y / ntiles; nt = blockIdx.y % ntiles; }
    else            { e = 0;                   nt = blockIdx.y; }
    const int m0 = mt * MT, n0 = nt * 64;
    int rows, base = 0;
    if (AMODE != 0) { rows = g_cnt[e]; base = g_off[e]; if (m0 >= rows) return; }
    else rows = M;

    const fp16* bsrc[NB];
    bsrc[0] = B0 + (size_t)e * bStride;
    if (MODE == 1) bsrc[1] = B1 + (size_t)e * bStride;

    const int tid = threadIdx.x, lane = tid & 31, wid = tid >> 5;
    const int wr = (MT == 128) ? (wid >> 1) : (wid >> 2);
    const int wc = (MT == 128) ? (wid & 1)  : (wid & 3);

    const uint32_t smbase = (uint32_t)__cvta_generic_to_shared(sm);

    // A cp.async: MT rows x 4 chunks(16B)
    const fp16* aSrc[ACH];
    uint32_t aDst[ACH];
    bool aOk[ACH];
    #pragma unroll
    for (int i = 0; i < ACH; i++) {
        int idx = i*256 + tid;
        int r = idx >> 2, q = idx & 3;
        int gm = m0 + r;
        bool ok = gm < rows;
        int row = 0;
        if (ok) {
            if (AMODE == 1)      row = g_list[base + gm];
            else if (AMODE == 2) row = base + gm;
            else                 row = gm;
        }
        aSrc[i] = A + (size_t)row * lda + q*8;
        aOk[i]  = ok;
        aDst[i] = (uint32_t)((r*40 + q*8) * 2);
    }
    // B cp.async: NB arrays x 64 rows x 4 chunks
    const fp16* bSrc[NB];
    uint32_t bDst[NB];
    #pragma unroll
    for (int i = 0; i < NB; i++) {
        int idx = i*256 + tid;
        int arr = idx >> 8, rem = idx & 255;
        int r = rem >> 2, q = rem & 3;
        bSrc[i] = bsrc[arr] + (size_t)(n0 + r) * K + q*8;
        bDst[i] = (uint32_t)((OFF_B + arr*64*40 + r*40 + q*8) * 2);
    }

    float accg[2][FN][4];
    float accu[MODE == 1 ? 2 : 1][FN][4];
    #pragma unroll
    for (int fm = 0; fm < 2; fm++)
        #pragma unroll
        for (int fn = 0; fn < FN; fn++)
            #pragma unroll
            for (int q = 0; q < 4; q++) {
                accg[fm][fn][q] = 0.f;
                if (MODE == 1) accu[fm][fn][q] = 0.f;
            }

    const int nk = K / 32;

    // prologue: stages 0,1
    #pragma unroll
    for (int s = 0; s < 2; s++) {
        const uint32_t sb = smbase + (uint32_t)(s * STG * 2);
        const int k0 = s * 32;
        #pragma unroll
        for (int i = 0; i < ACH; i++) cp16(sb + aDst[i], aSrc[i] + k0, aOk[i]);
        #pragma unroll
        for (int i = 0; i < NB; i++) cp16(sb + bDst[i], bSrc[i] + k0, true);
        cp_commit();
    }

    for (int kt = 0; kt < nk; kt++) {
        const int st = kt % 3;
        if (kt + 1 < nk) cp_wait<1>(); else cp_wait<0>();
        __syncthreads();   // all warps done reading stage (kt-1)%3 == (kt+2)%3
        if (kt + 2 < nk) {
            const int k0 = (kt + 2) * 32;
            const uint32_t sb = smbase + (uint32_t)(((kt + 2) % 3) * STG * 2);
            #pragma unroll
            for (int i = 0; i < ACH; i++) cp16(sb + aDst[i], aSrc[i] + k0, aOk[i]);
            #pragma unroll
            for (int i = 0; i < NB; i++) cp16(sb + bDst[i], bSrc[i] + k0, true);
            cp_commit();
        }

        fp16* pA = sm + st * STG;
        fp16* pB = pA + OFF_B;

        #pragma unroll
        for (int kk = 0; kk < 32; kk += 16) {
            uint32_t fa[2][4];
            #pragma unroll
            for (int fm = 0; fm < 2; fm++) {
                int arow = wr*32 + fm*16 + (lane & 15);
                int acol = kk + (lane >> 4) * 8;
                ldsm_x4(fa[fm], pA + arow*40 + acol);
            }
            uint32_t bfr[NB][FN][2];
            #pragma unroll
            for (int fp = 0; fp < FN/2; fp++) {
                int brow = wc*(FN*8) + fp*16 + ((lane >> 4) << 3) + (lane & 7);
                int bcol = kk + ((lane >> 3) & 1) * 8;
                #pragma unroll
                for (int arr = 0; arr < NB; arr++) {
                    uint32_t r4[4];
                    ldsm_x4(r4, pB + arr*64*40 + brow*40 + bcol);
                    bfr[arr][2*fp+0][0] = r4[0]; bfr[arr][2*fp+0][1] = r4[1];
                    bfr[arr][2*fp+1][0] = r4[2]; bfr[arr][2*fp+1][1] = r4[3];
                }
            }
            #pragma unroll
            for (int fn = 0; fn < FN; fn++) {
                #pragma unroll
                for (int fm = 0; fm < 2; fm++) {
                    mma16816h(accg[fm][fn], fa[fm], bfr[0][fn]);
                    if (MODE == 1) mma16816h(accu[fm][fn], fa[fm], bfr[1][fn]);
                }
            }
        }
    }

    // epilogue
    #pragma unroll
    for (int fm = 0; fm < 2; fm++) {
        int rbase = m0 + wr*32 + fm*16 + (lane >> 2);
        #pragma unroll
        for (int half = 0; half < 2; half++) {
            int gm = rbase + half*8;
            if (AMODE != 0 && gm >= rows) continue;
            float w = 0.f;
            if (MODE == 2) w = g_lw[base + gm];
            #pragma unroll
            for (int fn = 0; fn < FN; fn++) {
                int col = n0 + wc*(FN*8) + fn*8 + (lane & 3)*2;
                float c0 = accg[fm][fn][half*2+0];
                float c1 = accg[fm][fn][half*2+1];
                if (MODE == 0) {
                    *(float2*)&C[(size_t)gm * ldc + col] = make_float2(c0, c1);
                } else if (MODE == 1) {
                    float u0 = accu[fm][fn][half*2+0];
                    float u1 = accu[fm][fn][half*2+1];
                    float s0 = c0 / (1.f + __expf(-c0)) * u0;
                    float s1 = c1 / (1.f + __expf(-c1)) * u1;
                    int rc = (AMODE != 0) ? (base + gm) : gm;
                    __half2 hh = __halves2half2(__float2half_rn(s0), __float2half_rn(s1));
                    *(__half2*)&Cq[(size_t)rc * ldc + col] = hh;
                } else { // MODE == 2: weighted fp16 slot store
                    int rc = base + gm;
                    __half2 hh = __halves2half2(__float2half_rn(c0 * w), __float2half_rn(c1 * w));
                    *(__half2*)&Cq[(size_t)rc * ldc + col] = hh;
                }
            }
        }
    }
}

// ---------------- final gather-reduce (fp16 dout) ----------------
__global__ void reduce_out(float* __restrict__ out) {
    int t = blockIdx.x;
    int p[TOPK];
    #pragma unroll
    for (int k = 0; k < TOPK; k++) p[k] = g_pos[t*TOPK + k];
    float4* o4 = (float4*)(out + (size_t)t * Hh);
    for (int c = threadIdx.x; c < Hh/4; c += blockDim.x) {
        float4 v = o4[c];
        #pragma unroll
        for (int k = 0; k < TOPK; k++) {
            uint2 d2 = ((const uint2*)(g_dout16 + (size_t)p[k] * Hh))[c];
            __half2 h01 = *(__half2*)&d2.x;
            __half2 h23 = *(__half2*)&d2.y;
            float2 f01 = __half22float2(h01);
            float2 f23 = __half22float2(h23);
            v.x += f01.x; v.y += f01.y; v.z += f23.x; v.w += f23.y;
        }
        o4[c] = v;
    }
}

// ---------------- launch ----------------
extern "C" void kernel_launch(void* const* d_in, const int* in_sizes, int n_in,
                              void* d_out, int out_size) {
    const float* x      = (const float*)d_in[0];
    const float* wr     = (const float*)d_in[1];
    const float* wgexp  = (const float*)d_in[2];
    const float* wuexp  = (const float*)d_in[3];
    const float* wdexp  = (const float*)d_in[4];
    const float* wsg    = (const float*)d_in[5];
    const float* wsu    = (const float*)d_in[6];
    const float* wsd    = (const float*)d_in[7];
    float* out = (float*)d_out;

    fp16 *pWg,*pWu,*pWd,*pSg,*pSu,*pSd;
    fp16 *pX16,*pSh16,*pAct16,*pDout16;
    cudaGetSymbolAddress((void**)&pWg, g_Wg);
    cudaGetSymbolAddress((void**)&pWu, g_Wu);
    cudaGetSymbolAddress((void**)&pWd, g_Wd);
    cudaGetSymbolAddress((void**)&pSg, g_Sg);
    cudaGetSymbolAddress((void**)&pSu, g_Su);
    cudaGetSymbolAddress((void**)&pSd, g_Sd);
    cudaGetSymbolAddress((void**)&pX16, g_x16);
    cudaGetSymbolAddress((void**)&pSh16, g_sh16);
    cudaGetSymbolAddress((void**)&pAct16, g_act16);
    cudaGetSymbolAddress((void**)&pDout16, g_dout16);

    const int SM_U128 = (128*40 + 2*64*40) * 2 * 3;  // <1,0,128>: 61440 B
    const int SM_U64  = (64*40  + 2*64*40) * 2 * 3;  // <1,1,64>:  46080 B
    const int SM_D128 = (128*40 + 1*64*40) * 2 * 3;  // <0,0,128>: 46080 B
    const int SM_D64  = (64*40  + 1*64*40) * 2 * 3;  // <2,2,64>:  30720 B
    cudaFuncSetAttribute(mma2<1,0,128>, cudaFuncAttributeMaxDynamicSharedMemorySize, SM_U128);
    cudaFuncSetAttribute(mma2<1,1,64>,  cudaFuncAttributeMaxDynamicSharedMemorySize, SM_U64);
    cudaFuncSetAttribute(mma2<0,0,128>, cudaFuncAttributeMaxDynamicSharedMemorySize, SM_D128);
    cudaFuncSetAttribute(mma2<2,2,64>,  cudaFuncAttributeMaxDynamicSharedMemorySize, SM_D64);

    // 1) convert x + shared weights (also zeroes expert counters)
    const int NCVT = (BT*Hh + 2*FFN*Hh + Hh*FFN) / 4;
    cvt_all<<<(NCVT + 255)/256, 256>>>(x, wsg, wsu, wsd);
    // 2) router GEMM + top-k fused (fp32 — top-k ordering must match reference)
    router_fused<<<BT/64, 256>>>(x, wr);
    // 3) grouped compaction (scan folded in)
    build_lists<<<NEXP, 256>>>();
    // 4) expert weight repack (vectorized 64x64 transpose)
    repack64<2><<<dim3(Ee, Hh/64), 256>>>(wgexp, wuexp, pWg, pWu,
                                          Ee*NEXP, (size_t)Ee*Hh, Hh);
    repack64<1><<<dim3(Hh, Ee/64), 256>>>(wdexp, nullptr, pWd, nullptr,
                                          Hh*NEXP, (size_t)Hh*Ee, Ee);
    // 5) up GEMMs (silu(g)*u -> fp16)
    mma2<1,0,128><<<dim3(BT/128, FFN/64), 256, SM_U128>>>(
        pX16, Hh, pSg, pSu, 0,
        nullptr, pSh16, FFN, BT, Hh, 1);
    mma2<1,1,64><<<dim3(BT/64, NEXP*(Ee/64)), 256, SM_U64>>>(
        pX16, Hh, pWg, pWu, (size_t)Ee*Hh,
        nullptr, pAct16, Ee, 0, Hh, Ee/64);
    // 6) down GEMMs
    mma2<0,0,128><<<dim3(BT/128, Hh/64), 256, SM_D128>>>(
        pSh16, FFN, pSd, nullptr, 0,
        out, nullptr, Hh, BT, FFN, 1);
    mma2<2,2,64><<<dim3(BT/64, NEXP*(Hh/64)), 256, SM_D64>>>(
        pAct16, Ee, pWd, nullptr, (size_t)Hh*Ee,
        nullptr, pDout16, Hh, 0, Ee, Hh/64);
    // 7) combine routed + shared
    reduce_out<<<BT, 256>>>(out);
}

// round 16
// speedup vs baseline: 1.0558x; 1.0558x over previous
#include <cuda_runtime.h>
#include <cuda_fp16.h>
#include <cstdint>
#include <cstddef>

#define BT   2048
#define Hh   1280
#define Ee   896
#define NEXP 64
#define TOPK 6
#define FFN  1792
#define TOT  (BT*TOPK)

typedef __half fp16;

// ---------------- device scratch ----------------
__device__ fp16 g_Wg[(size_t)NEXP*Ee*Hh];   // [exp][e][h]
__device__ fp16 g_Wu[(size_t)NEXP*Ee*Hh];
__device__ fp16 g_Wd[(size_t)NEXP*Hh*Ee];   // [exp][h][e]
__device__ fp16 g_Sg[(size_t)FFN*Hh];
__device__ fp16 g_Su[(size_t)FFN*Hh];
__device__ fp16 g_Sd[(size_t)Hh*FFN];
__device__ fp16 g_x16[(size_t)BT*Hh];
__device__ fp16 g_sh16[(size_t)BT*FFN];
__device__ fp16 g_act16[(size_t)TOT*Ee];
__device__ fp16 g_dout16[(size_t)TOT*Hh];
// router
__device__ int   g_topi[TOT];
__device__ float g_topw[TOT];
__device__ int   g_cnt[NEXP];
__device__ int   g_off[NEXP];
__device__ int   g_list[TOT];
__device__ float g_lw[TOT];
__device__ int   g_pos[TOT];

// ---------------- fused convert (x + shared weights) + zero counters ----------------
__global__ void cvt_all(const float* __restrict__ x,
                        const float* __restrict__ wsg,
                        const float* __restrict__ wsu,
                        const float* __restrict__ wsd) {
    if (blockIdx.x == 0 && threadIdx.x < NEXP) g_cnt[threadIdx.x] = 0;
    const int C0 = BT*Hh/4;            // x
    const int C1 = C0 + FFN*Hh/4;      // sg
    const int C2 = C1 + FFN*Hh/4;      // su
    const int C3 = C2 + Hh*FFN/4;      // sd
    int i = blockIdx.x * blockDim.x + threadIdx.x;
    if (i >= C3) return;
    const float* src; fp16* dst; int j;
    if (i < C0)      { src = x;   dst = g_x16; j = i; }
    else if (i < C1) { src = wsg; dst = g_Sg;  j = i - C0; }
    else if (i < C2) { src = wsu; dst = g_Su;  j = i - C1; }
    else             { src = wsd; dst = g_Sd;  j = i - C2; }
    float4 v = ((const float4*)src)[j];
    __half2 a = __halves2half2(__float2half_rn(v.x), __float2half_rn(v.y));
    __half2 b = __halves2half2(__float2half_rn(v.z), __float2half_rn(v.w));
    uint2 p; p.x = *(uint32_t*)&a; p.y = *(uint32_t*)&b;
    ((uint2*)dst)[j] = p;
}

// ---------------- fused router GEMM + top-k ----------------
__global__ __launch_bounds__(256) void router_fused(
    const float* __restrict__ A, const float* __restrict__ B)
{
    const int m0 = blockIdx.x * 64;
    __shared__ __align__(16) float As[16][68];
    __shared__ __align__(16) float Bs[16][68];
    __shared__ float L[64][65];
    const int tid = threadIdx.x;
    const int tx = tid & 15, ty = tid >> 4;
    float acc[4][4];
    #pragma unroll
    for (int i = 0; i < 4; i++) for (int j = 0; j < 4; j++) acc[i][j] = 0.f;
    const int aCol = tid & 15, aRow0 = tid >> 4;
    for (int k0 = 0; k0 < Hh; k0 += 16) {
        #pragma unroll
        for (int i = 0; i < 4; i++)
            As[aCol][aRow0 + 16*i] = A[(size_t)(m0 + aRow0 + 16*i)*Hh + k0 + aCol];
        #pragma unroll
        for (int i = 0; i < 4; i++)
            Bs[aCol][aRow0 + 16*i] = B[(size_t)(aRow0 + 16*i)*Hh + k0 + aCol];
        __syncthreads();
        #pragma unroll
        for (int kk = 0; kk < 16; kk++) {
            float4 a4 = *(const float4*)&As[kk][ty*4];
            float4 b4 = *(const float4*)&Bs[kk][tx*4];
            float av[4] = {a4.x,a4.y,a4.z,a4.w};
            float bv[4] = {b4.x,b4.y,b4.z,b4.w};
            #pragma unroll
            for (int i = 0; i < 4; i++) for (int j = 0; j < 4; j++) acc[i][j] += av[i]*bv[j];
        }
        __syncthreads();
    }
    #pragma unroll
    for (int i = 0; i < 4; i++)
        #pragma unroll
        for (int j = 0; j < 4; j++)
            L[ty*4 + i][tx*4 + j] = acc[i][j];
    __syncthreads();

    const int lane = tid & 31, wid = tid >> 5;
    const float NEG = __int_as_float(0xff800000);
    for (int s = 0; s < 8; s++) {
        int tl = wid * 8 + s;
        int t  = m0 + tl;
        float v0 = L[tl][lane];
        float v1 = L[tl][32 + lane];
        int i0 = lane, i1 = lane + 32;
        float bv[TOPK]; int bi[TOPK];
        #pragma unroll
        for (int k = 0; k < TOPK; k++) {
            float mv; int mi;
            if (v0 > v1 || (v0 == v1 && i0 < i1)) { mv = v0; mi = i0; } else { mv = v1; mi = i1; }
            #pragma unroll
            for (int o = 16; o > 0; o >>= 1) {
                float ov = __shfl_xor_sync(0xffffffffu, mv, o);
                int   oi = __shfl_xor_sync(0xffffffffu, mi, o);
                if (ov > mv || (ov == mv && oi < mi)) { mv = ov; mi = oi; }
            }
            bv[k] = mv; bi[k] = mi;
            if (i0 == mi) v0 = NEG;
            if (i1 == mi) v1 = NEG;
        }
        float mx = bv[0];
        float sum = 0.f, ev[TOPK];
        #pragma unroll
        for (int k = 0; k < TOPK; k++) { ev[k] = __expf(bv[k] - mx); sum += ev[k]; }
        if (lane < TOPK) {
            g_topi[t*TOPK + lane] = bi[lane];
            g_topw[t*TOPK + lane] = ev[lane] / sum;
            atomicAdd(&g_cnt[bi[lane]], 1);
        }
    }
}

// ---------------- build lists (scan folded in) ----------------
__global__ void build_lists() {
    int e = blockIdx.x;
    int tid = threadIdx.x;
    int lane = tid & 31, wid = tid >> 5;
    __shared__ int wcnt[8], wpre[8], stot, base_s;
    if (tid == 0) {
        int a = 0;
        for (int n = 0; n < e; n++) a += g_cnt[n];
        base_s = a;
        g_off[e] = a;
    }
    __syncthreads();
    int base = base_s;
    int run = 0;
    for (int s0 = 0; s0 < TOT; s0 += 256) {
        int s = s0 + tid;
        bool p = (s < TOT) && (g_topi[s] == e);
        unsigned b = __ballot_sync(0xffffffffu, p);
        int wp = __popc(b & ((1u << lane) - 1u));
        if (lane == 0) wcnt[wid] = __popc(b);
        __syncthreads();
        if (tid == 0) {
            int a = 0;
            for (int w = 0; w < 8; w++) { wpre[w] = a; a += wcnt[w]; }
            stot = a;
        }
        __syncthreads();
        if (p) {
            int pos = base + run + wpre[wid] + wp;
            g_list[pos] = s / TOPK;
            g_lw[pos]   = g_topw[s];
            g_pos[s]    = pos;
        }
        run += stot;
        __syncthreads();
    }
}

// ---------------- vectorized 64x64 transpose-convert repack ----------------
template<int NARR>
__global__ __launch_bounds__(256) void repack64(
    const float* __restrict__ s0, const float* __restrict__ s1,
    fp16* __restrict__ d0, fp16* __restrict__ d1,
    int S1, size_t S2, int S3)
{
    __shared__ float smA[64][65];
    __shared__ float smB[NARR == 2 ? 64 : 1][NARR == 2 ? 65 : 1];
    const int F = blockIdx.x;
    const int dd0 = blockIdx.y * 64;
    const int t = threadIdx.x;

    #pragma unroll
    for (int i = 0; i < 4; i++) {
        int idx = i*256 + t;
        int r = idx >> 4, q = idx & 15;
        size_t so = (size_t)(dd0 + r) * S1 + (size_t)F * 64 + q*4;
        float4 v = *(const float4*)(s0 + so);
        smA[q*4+0][r] = v.x; smA[q*4+1][r] = v.y;
        smA[q*4+2][r] = v.z; smA[q*4+3][r] = v.w;
        if (NARR == 2) {
            float4 u = *(const float4*)(s1 + so);
            smB[q*4+0][r] = u.x; smB[q*4+1][r] = u.y;
            smB[q*4+2][r] = u.z; smB[q*4+3][r] = u.w;
        }
    }
    __syncthreads();

    #pragma unroll
    for (int i = 0; i < 2; i++) {
        int idx = i*256 + t;
        int xr = idx >> 3, hb = idx & 7;
        fp16 h8[8];
        #pragma unroll
        for (int c = 0; c < 8; c++) h8[c] = __float2half_rn(smA[xr][hb*8 + c]);
        size_t doff = (size_t)xr * S2 + (size_t)F * S3 + dd0 + hb*8;
        *(uint4*)(d0 + doff) = *(uint4*)h8;
        if (NARR == 2) {
            #pragma unroll
            for (int c = 0; c < 8; c++) h8[c] = __float2half_rn(smB[xr][hb*8 + c]);
            *(uint4*)(d1 + doff) = *(uint4*)h8;
        }
    }
}

// ---------------- MMA / cp.async helpers ----------------
__device__ __forceinline__ void ldsm_x4(uint32_t* r, const void* p) {
    uint32_t a = (uint32_t)__cvta_generic_to_shared(p);
    asm volatile("ldmatrix.sync.aligned.m8n8.x4.shared.b16 {%0,%1,%2,%3}, [%4];"
        : "=r"(r[0]), "=r"(r[1]), "=r"(r[2]), "=r"(r[3]) : "r"(a));
}
__device__ __forceinline__ void mma16816h(float* d, const uint32_t* a, const uint32_t* b) {
    asm volatile("mma.sync.aligned.m16n8k16.row.col.f32.f16.f16.f32 "
        "{%0,%1,%2,%3}, {%4,%5,%6,%7}, {%8,%9}, {%0,%1,%2,%3};"
        : "+f"(d[0]), "+f"(d[1]), "+f"(d[2]), "+f"(d[3])
        : "r"(a[0]), "r"(a[1]), "r"(a[2]), "r"(a[3]), "r"(b[0]), "r"(b[1]));
}
__device__ __forceinline__ void cp16(uint32_t dst, const void* src, bool pred) {
    int sz = pred ? 16 : 0;
    asm volatile("cp.async.ca.shared.global [%0], [%1], 16, %2;"
        :: "r"(dst), "l"(src), "r"(sz));
}
__device__ __forceinline__ void cp_commit() { asm volatile("cp.async.commit_group;" ::: "memory"); }
template<int N> __device__ __forceinline__ void cp_wait() { asm volatile("cp.async.wait_group %0;" :: "n"(N) : "memory"); }

// ---------------- single-fp16 MMA GEMM ----------------
// 128x64x32 tile, 8 warps (4x2, warp 32x32), 3-stage cp.async ring,
// single __syncthreads per k-iter, 2 CTAs/SM.
// MODE: 0 fp32 store, 1 dual-B silu(g)*u -> fp16 store, 2 weighted slot fp16 store
// AMODE: 0 plain rows, 1 gather via g_list (store rows = slots), 2 rows are slots
template<int MODE, int AMODE>
__global__ __launch_bounds__(256, 2) void mma2(
    const fp16* __restrict__ A, int lda,
    const fp16* __restrict__ B0, const fp16* __restrict__ B1,
    size_t bStride,
    float* __restrict__ C, fp16* __restrict__ Cq,
    int ldc, int M, int K, int ntiles)
{
    constexpr int NB = (MODE == 1) ? 2 : 1;
    constexpr int OFF_B = 128*40;
    constexpr int STG   = 128*40 + NB*64*40;
    extern __shared__ __align__(16) fp16 sm[];

    const int mt = blockIdx.x;
    int e, nt;
    if (AMODE != 0) { e = blockIdx.y / ntiles; nt = blockIdx.y % ntiles; }
    else            { e = 0;                   nt = blockIdx.y; }
    const int m0 = mt * 128, n0 = nt * 64;
    int rows, base = 0;
    if (AMODE != 0) { rows = g_cnt[e]; base = g_off[e]; if (m0 >= rows) return; }
    else rows = M;

    const fp16* bsrc[NB];
    bsrc[0] = B0 + (size_t)e * bStride;
    if (MODE == 1) bsrc[1] = B1 + (size_t)e * bStride;

    const int tid = threadIdx.x, lane = tid & 31, wid = tid >> 5;
    const int wr = wid >> 1, wc = wid & 1;

    const uint32_t smbase = (uint32_t)__cvta_generic_to_shared(sm);

    // A cp.async: 128 rows x 4 chunks(16B) = 512 -> 2/thread
    const fp16* aSrc[2];
    uint32_t aDst[2];
    bool aOk[2];
    #pragma unroll
    for (int i = 0; i < 2; i++) {
        int idx = i*256 + tid;
        int r = idx >> 2, q = idx & 3;
        int gm = m0 + r;
        bool ok = gm < rows;
        int row = 0;
        if (ok) {
            if (AMODE == 1)      row = g_list[base + gm];
            else if (AMODE == 2) row = base + gm;
            else                 row = gm;
        }
        aSrc[i] = A + (size_t)row * lda + q*8;
        aOk[i]  = ok;
        aDst[i] = (uint32_t)((r*40 + q*8) * 2);
    }
    // B cp.async: NB arrays x 64 rows x 4 chunks
    const fp16* bSrc[NB];
    uint32_t bDst[NB];
    #pragma unroll
    for (int i = 0; i < NB; i++) {
        int idx = i*256 + tid;
        int arr = idx >> 8, rem = idx & 255;
        int r = rem >> 2, q = rem & 3;
        bSrc[i] = bsrc[arr] + (size_t)(n0 + r) * K + q*8;
        bDst[i] = (uint32_t)((OFF_B + arr*64*40 + r*40 + q*8) * 2);
    }

    float accg[2][4][4];
    float accu[MODE == 1 ? 2 : 1][4][4];
    #pragma unroll
    for (int fm = 0; fm < 2; fm++)
        #pragma unroll
        for (int fn = 0; fn < 4; fn++)
            #pragma unroll
            for (int q = 0; q < 4; q++) {
                accg[fm][fn][q] = 0.f;
                if (MODE == 1) accu[fm][fn][q] = 0.f;
            }

    const int nk = K / 32;

    // prologue: stages 0,1
    #pragma unroll
    for (int s = 0; s < 2; s++) {
        const uint32_t sb = smbase + (uint32_t)(s * STG * 2);
        const int k0 = s * 32;
        #pragma unroll
        for (int i = 0; i < 2; i++) cp16(sb + aDst[i], aSrc[i] + k0, aOk[i]);
        #pragma unroll
        for (int i = 0; i < NB; i++) cp16(sb + bDst[i], bSrc[i] + k0, true);
        cp_commit();
    }

    for (int kt = 0; kt < nk; kt++) {
        const int st = kt % 3;
        if (kt + 1 < nk) cp_wait<1>(); else cp_wait<0>();
        __syncthreads();   // orders last iter's reads of stage (kt+2)%3 before overwrite below
        if (kt + 2 < nk) {
            const int k0 = (kt + 2) * 32;
            const uint32_t sb = smbase + (uint32_t)(((kt + 2) % 3) * STG * 2);
            #pragma unroll
            for (int i = 0; i < 2; i++) cp16(sb + aDst[i], aSrc[i] + k0, aOk[i]);
            #pragma unroll
            for (int i = 0; i < NB; i++) cp16(sb + bDst[i], bSrc[i] + k0, true);
            cp_commit();
        }

        fp16* pA = sm + st * STG;
        fp16* pB = pA + OFF_B;

        #pragma unroll
        for (int kk = 0; kk < 32; kk += 16) {
            uint32_t fa[2][4];
            #pragma unroll
            for (int fm = 0; fm < 2; fm++) {
                int arow = wr*32 + fm*16 + (lane & 15);
                int acol = kk + (lane >> 4) * 8;
                ldsm_x4(fa[fm], pA + arow*40 + acol);
            }
            uint32_t bfr[NB][4][2];
            #pragma unroll
            for (int fp = 0; fp < 2; fp++) {
                int brow = wc*32 + fp*16 + ((lane >> 4) << 3) + (lane & 7);
                int bcol = kk + ((lane >> 3) & 1) * 8;
                #pragma unroll
                for (int arr = 0; arr < NB; arr++) {
                    uint32_t r4[4];
                    ldsm_x4(r4, pB + arr*64*40 + brow*40 + bcol);
                    bfr[arr][2*fp+0][0] = r4[0]; bfr[arr][2*fp+0][1] = r4[1];
                    bfr[arr][2*fp+1][0] = r4[2]; bfr[arr][2*fp+1][1] = r4[3];
                }
            }
            #pragma unroll
            for (int fn = 0; fn < 4; fn++) {
                #pragma unroll
                for (int fm = 0; fm < 2; fm++) {
                    mma16816h(accg[fm][fn], fa[fm], bfr[0][fn]);
                    if (MODE == 1) mma16816h(accu[fm][fn], fa[fm], bfr[1][fn]);
                }
            }
        }
    }

    // epilogue
    #pragma unroll
    for (int fm = 0; fm < 2; fm++) {
        int rbase = m0 + wr*32 + fm*16 + (lane >> 2);
        #pragma unroll
        for (int half = 0; half < 2; half++) {
            int gm = rbase + half*8;
            if (AMODE != 0 && gm >= rows) continue;
            float w = 0.f;
            if (MODE == 2) w = g_lw[base + gm];
            #pragma unroll
            for (int fn = 0; fn < 4; fn++) {
                int col = n0 + wc*32 + fn*8 + (lane & 3)*2;
                float c0 = accg[fm][fn][half*2+0];
                float c1 = accg[fm][fn][half*2+1];
                if (MODE == 0) {
                    *(float2*)&C[(size_t)gm * ldc + col] = make_float2(c0, c1);
                } else if (MODE == 1) {
                    float u0 = accu[fm][fn][half*2+0];
                    float u1 = accu[fm][fn][half*2+1];
                    float s0 = c0 / (1.f + __expf(-c0)) * u0;
                    float s1 = c1 / (1.f + __expf(-c1)) * u1;
                    int rc = (AMODE != 0) ? (base + gm) : gm;
                    __half2 hh = __halves2half2(__float2half_rn(s0), __float2half_rn(s1));
                    *(__half2*)&Cq[(size_t)rc * ldc + col] = hh;
                } else { // MODE == 2: weighted fp16 slot store
                    int rc = base + gm;
                    __half2 hh = __halves2half2(__float2half_rn(c0 * w), __float2half_rn(c1 * w));
                    *(__half2*)&Cq[(size_t)rc * ldc + col] = hh;
                }
            }
        }
    }
}

// ---------------- final gather-reduce (fp16 dout) ----------------
__global__ void reduce_out(float* __restrict__ out) {
    int t = blockIdx.x;
    int p[TOPK];
    #pragma unroll
    for (int k = 0; k < TOPK; k++) p[k] = g_pos[t*TOPK + k];
    float4* o4 = (float4*)(out + (size_t)t * Hh);
    for (int c = threadIdx.x; c < Hh/4; c += blockDim.x) {
        float4 v = o4[c];
        #pragma unroll
        for (int k = 0; k < TOPK; k++) {
            uint2 d2 = ((const uint2*)(g_dout16 + (size_t)p[k] * Hh))[c];
            __half2 h01 = *(__half2*)&d2.x;
            __half2 h23 = *(__half2*)&d2.y;
            float2 f01 = __half22float2(h01);
            float2 f23 = __half22float2(h23);
            v.x += f01.x; v.y += f01.y; v.z += f23.x; v.w += f23.y;
        }
        o4[c] = v;
    }
}

// ---------------- launch ----------------
extern "C" void kernel_launch(void* const* d_in, const int* in_sizes, int n_in,
                              void* d_out, int out_size) {
    const float* x      = (const float*)d_in[0];
    const float* wr     = (const float*)d_in[1];
    const float* wgexp  = (const float*)d_in[2];
    const float* wuexp  = (const float*)d_in[3];
    const float* wdexp  = (const float*)d_in[4];
    const float* wsg    = (const float*)d_in[5];
    const float* wsu    = (const float*)d_in[6];
    const float* wsd    = (const float*)d_in[7];
    float* out = (float*)d_out;

    fp16 *pWg,*pWu,*pWd,*pSg,*pSu,*pSd;
    fp16 *pX16,*pSh16,*pAct16,*pDout16;
    cudaGetSymbolAddress((void**)&pWg, g_Wg);
    cudaGetSymbolAddress((void**)&pWu, g_Wu);
    cudaGetSymbolAddress((void**)&pWd, g_Wd);
    cudaGetSymbolAddress((void**)&pSg, g_Sg);
    cudaGetSymbolAddress((void**)&pSu, g_Su);
    cudaGetSymbolAddress((void**)&pSd, g_Sd);
    cudaGetSymbolAddress((void**)&pX16, g_x16);
    cudaGetSymbolAddress((void**)&pSh16, g_sh16);
    cudaGetSymbolAddress((void**)&pAct16, g_act16);
    cudaGetSymbolAddress((void**)&pDout16, g_dout16);

    const int SM1 = (128*40 + 2*64*40) * 2 * 3;  // MODE=1: 61440 B
    const int SM0 = (128*40 + 1*64*40) * 2 * 3;  // MODE=0/2: 46080 B
    cudaFuncSetAttribute(mma2<1,0>, cudaFuncAttributeMaxDynamicSharedMemorySize, SM1);
    cudaFuncSetAttribute(mma2<1,1>, cudaFuncAttributeMaxDynamicSharedMemorySize, SM1);
    cudaFuncSetAttribute(mma2<0,0>, cudaFuncAttributeMaxDynamicSharedMemorySize, SM0);
    cudaFuncSetAttribute(mma2<2,2>, cudaFuncAttributeMaxDynamicSharedMemorySize, SM0);

    // 1) convert x + shared weights (also zeroes expert counters)
    const int NCVT = (BT*Hh + 2*FFN*Hh + Hh*FFN) / 4;
    cvt_all<<<(NCVT + 255)/256, 256>>>(x, wsg, wsu, wsd);
    // 2) router GEMM + top-k fused (fp32 — top-k ordering must match reference)
    router_fused<<<BT/64, 256>>>(x, wr);
    // 3) grouped compaction (scan folded in)
    build_lists<<<NEXP, 256>>>();
    // 4) expert weight repack (vectorized 64x64 transpose)
    repack64<2><<<dim3(Ee, Hh/64), 256>>>(wgexp, wuexp, pWg, pWu,
                                          Ee*NEXP, (size_t)Ee*Hh, Hh);
    repack64<1><<<dim3(Hh, Ee/64), 256>>>(wdexp, nullptr, pWd, nullptr,
                                          Hh*NEXP, (size_t)Hh*Ee, Ee);
    // 5) up GEMMs (silu(g)*u -> fp16)
    mma2<1,0><<<dim3(BT/128, FFN/64), 256, SM1>>>(
        pX16, Hh, pSg, pSu, 0,
        nullptr, pSh16, FFN, BT, Hh, 1);
    mma2<1,1><<<dim3(BT/128, NEXP*(Ee/64)), 256, SM1>>>(
        pX16, Hh, pWg, pWu, (size_t)Ee*Hh,
        nullptr, pAct16, Ee, 0, Hh, Ee/64);
    // 6) down GEMMs
    mma2<0,0><<<dim3(BT/128, Hh/64), 256, SM0>>>(
        pSh16, FFN, pSd, nullptr, 0,
        out, nullptr, Hh, BT, FFN, 1);
    mma2<2,2><<<dim3(BT/128, NEXP*(Hh/64)), 256, SM0>>>(
        pAct16, Ee, pWd, nullptr, (size_t)Hh*Ee,
        nullptr, pDout16, Hh, 0, Ee, Hh/64);
    // 7) combine routed + shared
    reduce_out<<<BT, 256>>>(out);
}